// round 13
// baseline (speedup 1.0000x reference)
#include <cuda_runtime.h>
#include <math.h>
#include <stdint.h>

// ---------------- problem constants ----------------
#define T_TOKENS 4096
#define HDIM     1280
#define EXPERTS  63
#define IDIM     1280
#define TOPK     7
#define CAP      4096
#define ASSIGN   (T_TOKENS*TOPK)

// ---------------- GEMM tiling ----------------
#define BM 128
#define BN 128
#define BK 32
#define NSTAGE 3
#define ASTRIDE 36                         // 32+4 floats
#define BSTRIDE 136                        // 128+8 floats
#define A_FLOATS (BM*ASTRIDE)              // 4608
#define B_FLOATS (BK*BSTRIDE)              // 4352
#define STAGE_BYTES ((A_FLOATS + B_FLOATS)*4)   // 35840
#define B_OFF (A_FLOATS*4)
#define AR_BYTES 1024
#define SMEM_TOTAL (AR_BYTES + NSTAGE*STAGE_BYTES)  // 108544

// ---------------- scratch ----------------
__device__ float g_h_routed[(size_t)ASSIGN  * IDIM];
__device__ float g_h_shared[(size_t)T_TOKENS * IDIM];
__device__ float g_o_routed[(size_t)ASSIGN  * HDIM];
__device__ float g_o_shared[(size_t)T_TOKENS * HDIM];
__device__ int   g_cnt[64];
__device__ int   g_off[64];
__device__ int   g_tok[EXPERTS * CAP];
__device__ int   g_eidx[T_TOKENS * TOPK];
__device__ int   g_epos[T_TOKENS * TOPK];
__device__ float g_gate[T_TOKENS * TOPK];

// ---------------- helpers ----------------
__device__ __forceinline__ uint32_t smem_u32(const void* p) {
    uint32_t a;
    asm("{ .reg .u64 t; cvta.to.shared.u64 t, %1; cvt.u32.u64 %0, t; }" : "=r"(a) : "l"(p));
    return a;
}
__device__ __forceinline__ void cp16(uint32_t dst, const void* src) {
    asm volatile("cp.async.cg.shared.global [%0], [%1], 16;" :: "r"(dst), "l"(src));
}
__device__ __forceinline__ void cp_commit() { asm volatile("cp.async.commit_group;" ::: "memory"); }
__device__ __forceinline__ void cp_wait1()  { asm volatile("cp.async.wait_group 1;" ::: "memory"); }

__device__ __forceinline__ void mma_tf32(float* d, const float* a, float b0, float b1) {
    asm volatile(
        "mma.sync.aligned.m16n8k8.row.col.f32.tf32.tf32.f32 "
        "{%0,%1,%2,%3}, {%4,%5,%6,%7}, {%8,%9}, {%0,%1,%2,%3};\n"
        : "+f"(d[0]), "+f"(d[1]), "+f"(d[2]), "+f"(d[3])
        : "r"(__float_as_uint(a[0])), "r"(__float_as_uint(a[1])),
          "r"(__float_as_uint(a[2])), "r"(__float_as_uint(a[3])),
          "r"(__float_as_uint(b0)),   "r"(__float_as_uint(b1)));
}

__device__ __forceinline__ float gelu_exact(float v) {
    return 0.5f * v * (1.0f + erff(v * 0.70710678118654752f));
}

// ---------------- bookkeeping ----------------
__global__ void zero_kernel() { if (threadIdx.x < 64) g_cnt[threadIdx.x] = 0; }

// Tiled router: 64 blocks x 64 tokens. Stages x-tile and w-tile through smem,
// so router_w is read once per 64 tokens instead of once per token.
#define RTB 64
__global__ void __launch_bounds__(256) router_kernel(
    const float* __restrict__ x,
    const float* __restrict__ rw,
    const float* __restrict__ rb)
{
    __shared__ float xs[RTB][36];        // 32-h chunk, padded
    __shared__ float ws[32][68];         // 63 experts used, padded
    __shared__ float lg[RTB][64];        // logits
    const int tid = threadIdx.x;
    const int t0  = blockIdx.x * RTB;

    const int tok = tid >> 2;            // 0..63
    const int eg  = (tid & 3) * 16;      // expert group base: 0,16,32,48
    float acc[16];
    #pragma unroll
    for (int i = 0; i < 16; i++) acc[i] = (eg + i < EXPERTS) ? rb[eg + i] : 0.f;

    const int xr = tid >> 2, xq = tid & 3;      // x loader: token xr, quads xq, xq+4
    const int wh = tid >> 3, we0 = (tid & 7) * 8;

    for (int hc = 0; hc < HDIM; hc += 32) {
        __syncthreads();
        *(float4*)&xs[xr][xq * 4]      = *(const float4*)(x + (size_t)(t0 + xr) * HDIM + hc + xq * 4);
        *(float4*)&xs[xr][16 + xq * 4] = *(const float4*)(x + (size_t)(t0 + xr) * HDIM + hc + 16 + xq * 4);
        #pragma unroll
        for (int j = 0; j < 8; j++) {
            int e = we0 + j;
            if (e < EXPERTS) ws[wh][e] = rw[(size_t)(hc + wh) * EXPERTS + e];
        }
        __syncthreads();
        #pragma unroll 8
        for (int h = 0; h < 32; h++) {
            float xv = xs[tok][h];
            float4 w0 = *(const float4*)&ws[h][eg];
            float4 w1 = *(const float4*)&ws[h][eg + 4];
            float4 w2 = *(const float4*)&ws[h][eg + 8];
            float4 w3 = *(const float4*)&ws[h][eg + 12];
            acc[0]  = fmaf(xv, w0.x, acc[0]);  acc[1]  = fmaf(xv, w0.y, acc[1]);
            acc[2]  = fmaf(xv, w0.z, acc[2]);  acc[3]  = fmaf(xv, w0.w, acc[3]);
            acc[4]  = fmaf(xv, w1.x, acc[4]);  acc[5]  = fmaf(xv, w1.y, acc[5]);
            acc[6]  = fmaf(xv, w1.z, acc[6]);  acc[7]  = fmaf(xv, w1.w, acc[7]);
            acc[8]  = fmaf(xv, w2.x, acc[8]);  acc[9]  = fmaf(xv, w2.y, acc[9]);
            acc[10] = fmaf(xv, w2.z, acc[10]); acc[11] = fmaf(xv, w2.w, acc[11]);
            acc[12] = fmaf(xv, w3.x, acc[12]); acc[13] = fmaf(xv, w3.y, acc[13]);
            acc[14] = fmaf(xv, w3.z, acc[14]); acc[15] = fmaf(xv, w3.w, acc[15]);
        }
    }
    #pragma unroll
    for (int i = 0; i < 16; i++)
        if (eg + i < EXPERTS) lg[tok][eg + i] = acc[i];
    __syncthreads();

    // per-token softmax + top-7 + deterministic bucketing
    if (tid < RTB) {
        int t = t0 + tid;
        float l[EXPERTS];
        #pragma unroll
        for (int i = 0; i < EXPERTS; i++) l[i] = lg[tid][i];
        float mx = l[0];
        for (int i = 1; i < EXPERTS; i++) mx = fmaxf(mx, l[i]);
        float den = 0.f;
        for (int i = 0; i < EXPERTS; i++) den += expf(l[i] - mx);
        float inv = 1.f / den;
        #pragma unroll
        for (int k = 0; k < TOPK; k++) {
            int bi = 0; float bv = l[0];
            for (int i = 1; i < EXPERTS; i++)
                if (l[i] > bv) { bv = l[i]; bi = i; }
            float val = expf(bv - mx) * inv;
            int pos = atomicAdd(&g_cnt[bi], 1);
            g_tok[bi * CAP + pos] = t;
            g_eidx[t * TOPK + k] = bi;
            g_epos[t * TOPK + k] = pos;
            g_gate[t * TOPK + k] = val;
            l[bi] = -INFINITY;
        }
    }
}

__global__ void offsets_kernel() {
    if (threadIdx.x == 0) {
        int o = 0;
        for (int e = 0; e < EXPERTS; e++) { g_off[e] = o; o += g_cnt[e]; }
    }
}

// ---------------- pipelined mma.sync grouped GEMM ----------------
// 256 threads = 8 warps as 4(m) x 2(n); warp tile 32x64; CTA tile 128x128, BK=32.
template <int MODE>
__global__ void __launch_bounds__(256, 2) gemm_kernel(
    const float* __restrict__ x,
    const float* __restrict__ w1,  const float* __restrict__ b1,
    const float* __restrict__ w1s, const float* __restrict__ b1s,
    const float* __restrict__ w2,  const float* __restrict__ b2,
    const float* __restrict__ w2s, const float* __restrict__ b2s)
{
    const int  e   = blockIdx.z;
    const bool se  = (e == EXPERTS);
    const int  cnt = se ? T_TOKENS : g_cnt[e];
    const int  m0  = blockIdx.y * BM;
    if (m0 >= cnt) return;
    const int  n0  = blockIdx.x * BN;

    extern __shared__ char smem[];
    const float** Arow = (const float**)smem;
    const uint32_t sb = smem_u32(smem);
    const int tid = threadIdx.x;

    const float* Bp; const float* bias;
    if (MODE == 0) { Bp = se ? w1s : (w1 + (size_t)e * HDIM * IDIM); bias = se ? b1s : (b1 + (size_t)e * IDIM); }
    else           { Bp = se ? w2s : (w2 + (size_t)e * IDIM * HDIM); bias = se ? b2s : (b2 + (size_t)e * HDIM); }
    const int off_e = se ? 0 : g_off[e];

    for (int r = tid; r < BM; r += 256) {
        int rr = m0 + r; if (rr > cnt - 1) rr = cnt - 1;
        const float* p;
        if (MODE == 0) p = se ? (x + (size_t)rr * HDIM) : (x + (size_t)g_tok[e * CAP + rr] * HDIM);
        else           p = se ? (g_h_shared + (size_t)rr * IDIM) : (g_h_routed + (size_t)(off_e + rr) * IDIM);
        Arow[r] = p;
    }
    __syncthreads();

    // loaders: A row=tid>>1, 16 floats at (tid&1)*16; B row=tid>>3, 16 floats at (tid&7)*16
    const int a_row = tid >> 1, a_q = (tid & 1) * 16;
    const int b_row = tid >> 3, b_q = (tid & 7) * 16;
    auto load_chunk = [&](int c) {
        const uint32_t stg = sb + AR_BYTES + (uint32_t)(c % NSTAGE) * STAGE_BYTES;
        #pragma unroll
        for (int j = 0; j < 4; j++)
            cp16(stg + (uint32_t)(a_row * ASTRIDE + a_q + 4 * j) * 4,
                 Arow[a_row] + c * BK + a_q + 4 * j);
        #pragma unroll
        for (int j = 0; j < 4; j++)
            cp16(stg + B_OFF + (uint32_t)(b_row * BSTRIDE + b_q + 4 * j) * 4,
                 Bp + (size_t)(c * BK + b_row) * 1280 + n0 + b_q + 4 * j);
    };

    const int lane = tid & 31, wid = tid >> 5;
    const int wm = wid & 3, wn = wid >> 2;
    const int gr = lane >> 2, tg = lane & 3;

    float acc[2][8][4];
    #pragma unroll
    for (int a = 0; a < 2; a++)
        #pragma unroll
        for (int b = 0; b < 8; b++)
            #pragma unroll
            for (int c = 0; c < 4; c++) acc[a][b][c] = 0.f;

    load_chunk(0); cp_commit();
    load_chunk(1); cp_commit();

    const int NCH = 1280 / BK;   // 40
    for (int c = 0; c < NCH; c++) {
        cp_wait1();
        __syncthreads();
        if (c + 2 < NCH) load_chunk(c + 2);
        cp_commit();

        const float* As_ = (const float*)(smem + AR_BYTES + (c % NSTAGE) * STAGE_BYTES);
        const float* Bs_ = (const float*)((const char*)As_ + B_OFF);

        #pragma unroll
        for (int ks = 0; ks < BK; ks += 8) {
            float a[2][4];
            #pragma unroll
            for (int mf = 0; mf < 2; mf++) {
                int rb = wm * 32 + mf * 16;
                a[mf][0] = As_[(rb + gr)     * ASTRIDE + ks + tg];
                a[mf][1] = As_[(rb + gr + 8) * ASTRIDE + ks + tg];
                a[mf][2] = As_[(rb + gr)     * ASTRIDE + ks + tg + 4];
                a[mf][3] = As_[(rb + gr + 8) * ASTRIDE + ks + tg + 4];
            }
            #pragma unroll
            for (int nf = 0; nf < 8; nf++) {
                int col = wn * 64 + nf * 8 + gr;
                float b0 = Bs_[(ks + tg)     * BSTRIDE + col];
                float b1 = Bs_[(ks + tg + 4) * BSTRIDE + col];
                mma_tf32(acc[0][nf], a[0], b0, b1);
                mma_tf32(acc[1][nf], a[1], b0, b1);
            }
        }
    }

    float* obase;
    if (MODE == 0) obase = se ? g_h_shared : g_h_routed;
    else           obase = se ? g_o_shared : g_o_routed;

    #pragma unroll
    for (int mf = 0; mf < 2; mf++) {
        int rb = wm * 32 + mf * 16 + gr;
        #pragma unroll
        for (int half = 0; half < 2; half++) {
            int r = rb + half * 8;
            if (m0 + r >= cnt) continue;
            float* op = obase + (size_t)(off_e + m0 + r) * 1280 + n0;
            #pragma unroll
            for (int nf = 0; nf < 8; nf++) {
                int c0 = wn * 64 + nf * 8 + 2 * tg;
                float2 v;
                v.x = acc[mf][nf][half * 2 + 0] + bias[n0 + c0];
                v.y = acc[mf][nf][half * 2 + 1] + bias[n0 + c0 + 1];
                if (MODE == 0) { v.x = gelu_exact(v.x); v.y = gelu_exact(v.y); }
                *(float2*)(op + c0) = v;
            }
        }
    }
}

// ---------------- final gather-reduce ----------------
__global__ void reduce_kernel(const float* __restrict__ x, float* __restrict__ out) {
    int t = blockIdx.x;
    size_t col = 4 * (size_t)threadIdx.x;
    float4 acc = *(const float4*)(x + (size_t)t * HDIM + col);
    float4 sh  = *(const float4*)(g_o_shared + (size_t)t * HDIM + col);
    acc.x += sh.x; acc.y += sh.y; acc.z += sh.z; acc.w += sh.w;
    #pragma unroll
    for (int k = 0; k < TOPK; k++) {
        int e   = g_eidx[t * TOPK + k];
        int p   = g_epos[t * TOPK + k];
        float g = g_gate[t * TOPK + k];
        const float4 v = *(const float4*)(g_o_routed + (size_t)(g_off[e] + p) * HDIM + col);
        acc.x += g * v.x; acc.y += g * v.y; acc.z += g * v.z; acc.w += g * v.w;
    }
    *(float4*)(out + (size_t)t * HDIM + col) = acc;
}

// ---------------------------------------------------------------------------
extern "C" void kernel_launch(void* const* d_in, const int* in_sizes, int n_in,
                              void* d_out, int out_size) {
    const float* x   = (const float*)d_in[0];
    const float* w1s = (const float*)d_in[1];
    const float* b1s = (const float*)d_in[2];
    const float* w2s = (const float*)d_in[3];
    const float* b2s = (const float*)d_in[4];
    const float* rw  = (const float*)d_in[5];
    const float* rb  = (const float*)d_in[6];
    const float* w1  = (const float*)d_in[7];
    const float* b1  = (const float*)d_in[8];
    const float* w2  = (const float*)d_in[9];
    const float* b2  = (const float*)d_in[10];
    float* out = (float*)d_out;

    cudaFuncSetAttribute(gemm_kernel<0>, cudaFuncAttributeMaxDynamicSharedMemorySize, SMEM_TOTAL);
    cudaFuncSetAttribute(gemm_kernel<1>, cudaFuncAttributeMaxDynamicSharedMemorySize, SMEM_TOTAL);

    zero_kernel<<<1, 64>>>();
    router_kernel<<<T_TOKENS / RTB, 256>>>(x, rw, rb);
    offsets_kernel<<<1, 32>>>();

    dim3 g(IDIM / BN, T_TOKENS / BM, EXPERTS + 1);   // (10, 32, 64)
    gemm_kernel<0><<<g, 256, SMEM_TOTAL>>>(x, w1, b1, w1s, b1s, w2, b2, w2s, b2s);
    gemm_kernel<1><<<g, 256, SMEM_TOTAL>>>(x, w1, b1, w1s, b1s, w2, b2, w2s, b2s);

    reduce_kernel<<<T_TOKENS, 320>>>(x, out);
}

// round 17
// speedup vs baseline: 1.4207x; 1.4207x over previous
#include <cuda_runtime.h>
#include <math.h>
#include <stdint.h>

// ---------------- problem constants ----------------
#define T_TOKENS 4096
#define HDIM     1280
#define EXPERTS  63
#define IDIM     1280
#define TOPK     7
#define CAP      4096
#define ASSIGN   (T_TOKENS*TOPK)

// ---------------- GEMM tiling ----------------
#define BM 128
#define BN 128
#define BK 32
#define NSTAGE 3
#define ASTRIDE 36                         // 32+4 floats
#define BSTRIDE 136                        // 128+8 floats
#define A_FLOATS (BM*ASTRIDE)              // 4608
#define B_FLOATS (BK*BSTRIDE)              // 4352
#define STAGE_BYTES ((A_FLOATS + B_FLOATS)*4)   // 35840
#define B_OFF (A_FLOATS*4)
#define AR_BYTES 1024
#define SMEM_TOTAL (AR_BYTES + NSTAGE*STAGE_BYTES)  // 108544

// ---------------- scratch ----------------
__device__ float g_h_routed[(size_t)ASSIGN  * IDIM];
__device__ float g_h_shared[(size_t)T_TOKENS * IDIM];
__device__ float g_o_routed[(size_t)ASSIGN  * HDIM];
__device__ float g_o_shared[(size_t)T_TOKENS * HDIM];
__device__ int   g_cnt[64];
__device__ int   g_off[64];
__device__ int   g_tok[EXPERTS * CAP];
__device__ int   g_eidx[T_TOKENS * TOPK];
__device__ int   g_epos[T_TOKENS * TOPK];
__device__ float g_gate[T_TOKENS * TOPK];

// ---------------- helpers ----------------
__device__ __forceinline__ uint32_t smem_u32(const void* p) {
    uint32_t a;
    asm("{ .reg .u64 t; cvta.to.shared.u64 t, %1; cvt.u32.u64 %0, t; }" : "=r"(a) : "l"(p));
    return a;
}
__device__ __forceinline__ void cp16(uint32_t dst, const void* src) {
    asm volatile("cp.async.cg.shared.global [%0], [%1], 16;" :: "r"(dst), "l"(src));
}
__device__ __forceinline__ void cp_commit() { asm volatile("cp.async.commit_group;" ::: "memory"); }
__device__ __forceinline__ void cp_wait1()  { asm volatile("cp.async.wait_group 1;" ::: "memory"); }

__device__ __forceinline__ void mma_tf32(float* d, const float* a, float b0, float b1) {
    asm volatile(
        "mma.sync.aligned.m16n8k8.row.col.f32.tf32.tf32.f32 "
        "{%0,%1,%2,%3}, {%4,%5,%6,%7}, {%8,%9}, {%0,%1,%2,%3};\n"
        : "+f"(d[0]), "+f"(d[1]), "+f"(d[2]), "+f"(d[3])
        : "r"(__float_as_uint(a[0])), "r"(__float_as_uint(a[1])),
          "r"(__float_as_uint(a[2])), "r"(__float_as_uint(a[3])),
          "r"(__float_as_uint(b0)),   "r"(__float_as_uint(b1)));
}

__device__ __forceinline__ float gelu_exact(float v) {
    return 0.5f * v * (1.0f + erff(v * 0.70710678118654752f));
}

// ---------------- bookkeeping ----------------
__global__ void zero_kernel() { if (threadIdx.x < 64) g_cnt[threadIdx.x] = 0; }

// Tiled router (kept: measured faster than per-token router)
#define RTB 64
__global__ void __launch_bounds__(256) router_kernel(
    const float* __restrict__ x,
    const float* __restrict__ rw,
    const float* __restrict__ rb)
{
    __shared__ float xs[RTB][36];
    __shared__ float ws[32][68];
    __shared__ float lg[RTB][64];
    const int tid = threadIdx.x;
    const int t0  = blockIdx.x * RTB;

    const int tok = tid >> 2;
    const int eg  = (tid & 3) * 16;
    float acc[16];
    #pragma unroll
    for (int i = 0; i < 16; i++) acc[i] = (eg + i < EXPERTS) ? rb[eg + i] : 0.f;

    const int xr = tid >> 2, xq = tid & 3;
    const int wh = tid >> 3, we0 = (tid & 7) * 8;

    for (int hc = 0; hc < HDIM; hc += 32) {
        __syncthreads();
        *(float4*)&xs[xr][xq * 4]      = *(const float4*)(x + (size_t)(t0 + xr) * HDIM + hc + xq * 4);
        *(float4*)&xs[xr][16 + xq * 4] = *(const float4*)(x + (size_t)(t0 + xr) * HDIM + hc + 16 + xq * 4);
        #pragma unroll
        for (int j = 0; j < 8; j++) {
            int e = we0 + j;
            if (e < EXPERTS) ws[wh][e] = rw[(size_t)(hc + wh) * EXPERTS + e];
        }
        __syncthreads();
        #pragma unroll 8
        for (int h = 0; h < 32; h++) {
            float xv = xs[tok][h];
            float4 w0 = *(const float4*)&ws[h][eg];
            float4 w1 = *(const float4*)&ws[h][eg + 4];
            float4 w2 = *(const float4*)&ws[h][eg + 8];
            float4 w3 = *(const float4*)&ws[h][eg + 12];
            acc[0]  = fmaf(xv, w0.x, acc[0]);  acc[1]  = fmaf(xv, w0.y, acc[1]);
            acc[2]  = fmaf(xv, w0.z, acc[2]);  acc[3]  = fmaf(xv, w0.w, acc[3]);
            acc[4]  = fmaf(xv, w1.x, acc[4]);  acc[5]  = fmaf(xv, w1.y, acc[5]);
            acc[6]  = fmaf(xv, w1.z, acc[6]);  acc[7]  = fmaf(xv, w1.w, acc[7]);
            acc[8]  = fmaf(xv, w2.x, acc[8]);  acc[9]  = fmaf(xv, w2.y, acc[9]);
            acc[10] = fmaf(xv, w2.z, acc[10]); acc[11] = fmaf(xv, w2.w, acc[11]);
            acc[12] = fmaf(xv, w3.x, acc[12]); acc[13] = fmaf(xv, w3.y, acc[13]);
            acc[14] = fmaf(xv, w3.z, acc[14]); acc[15] = fmaf(xv, w3.w, acc[15]);
        }
    }
    #pragma unroll
    for (int i = 0; i < 16; i++)
        if (eg + i < EXPERTS) lg[tok][eg + i] = acc[i];
    __syncthreads();

    if (tid < RTB) {
        int t = t0 + tid;
        float l[EXPERTS];
        #pragma unroll
        for (int i = 0; i < EXPERTS; i++) l[i] = lg[tid][i];
        float mx = l[0];
        for (int i = 1; i < EXPERTS; i++) mx = fmaxf(mx, l[i]);
        float den = 0.f;
        for (int i = 0; i < EXPERTS; i++) den += expf(l[i] - mx);
        float inv = 1.f / den;
        #pragma unroll
        for (int k = 0; k < TOPK; k++) {
            int bi = 0; float bv = l[0];
            for (int i = 1; i < EXPERTS; i++)
                if (l[i] > bv) { bv = l[i]; bi = i; }
            float val = expf(bv - mx) * inv;
            int pos = atomicAdd(&g_cnt[bi], 1);
            g_tok[bi * CAP + pos] = t;
            g_eidx[t * TOPK + k] = bi;
            g_epos[t * TOPK + k] = pos;
            g_gate[t * TOPK + k] = val;
            l[bi] = -INFINITY;
        }
    }
}

__global__ void offsets_kernel() {
    if (threadIdx.x == 0) {
        int o = 0;
        for (int e = 0; e < EXPERTS; e++) { g_off[e] = o; o += g_cnt[e]; }
    }
}

// ---------------- pipelined mma.sync grouped GEMM ----------------
// BK=32, 3 stages; warp-coalesced quad-per-thread loaders
// (R13 regression root cause: 64B-strided lanes within one cp.async halved
//  sector efficiency -> L2 45.7%, tensor 38%. This version: lanes adjacent.)
template <int MODE>
__global__ void __launch_bounds__(256, 2) gemm_kernel(
    const float* __restrict__ x,
    const float* __restrict__ w1,  const float* __restrict__ b1,
    const float* __restrict__ w1s, const float* __restrict__ b1s,
    const float* __restrict__ w2,  const float* __restrict__ b2,
    const float* __restrict__ w2s, const float* __restrict__ b2s)
{
    const int  e   = blockIdx.z;
    const bool se  = (e == EXPERTS);
    const int  cnt = se ? T_TOKENS : g_cnt[e];
    const int  m0  = blockIdx.y * BM;
    if (m0 >= cnt) return;
    const int  n0  = blockIdx.x * BN;

    extern __shared__ char smem[];
    const float** Arow = (const float**)smem;
    const uint32_t sb = smem_u32(smem);
    const int tid = threadIdx.x;

    const float* Bp; const float* bias;
    if (MODE == 0) { Bp = se ? w1s : (w1 + (size_t)e * HDIM * IDIM); bias = se ? b1s : (b1 + (size_t)e * IDIM); }
    else           { Bp = se ? w2s : (w2 + (size_t)e * IDIM * HDIM); bias = se ? b2s : (b2 + (size_t)e * HDIM); }
    const int off_e = se ? 0 : g_off[e];

    for (int r = tid; r < BM; r += 256) {
        int rr = m0 + r; if (rr > cnt - 1) rr = cnt - 1;
        const float* p;
        if (MODE == 0) p = se ? (x + (size_t)rr * HDIM) : (x + (size_t)g_tok[e * CAP + rr] * HDIM);
        else           p = se ? (g_h_shared + (size_t)rr * IDIM) : (g_h_routed + (size_t)(off_e + rr) * IDIM);
        Arow[r] = p;
    }
    __syncthreads();

    // Coalesced loaders: quad-per-thread, adjacent lanes -> adjacent 16B quads.
    auto load_chunk = [&](int c) {
        const uint32_t stg = sb + AR_BYTES + (uint32_t)(c % NSTAGE) * STAGE_BYTES;
        #pragma unroll
        for (int i = 0; i < 4; i++) {
            int id  = tid + i * 256;          // 0..1023
            int row = id >> 3;                // 0..127
            int col = (id & 7) * 4;           // 0..28
            cp16(stg + (uint32_t)(row * ASTRIDE + col) * 4,
                 Arow[row] + c * BK + col);
        }
        #pragma unroll
        for (int i = 0; i < 4; i++) {
            int id  = tid + i * 256;          // 0..1023
            int row = id >> 5;                // 0..31
            int col = (id & 31) * 4;          // 0..124
            cp16(stg + B_OFF + (uint32_t)(row * BSTRIDE + col) * 4,
                 Bp + (size_t)(c * BK + row) * 1280 + n0 + col);
        }
    };

    const int lane = tid & 31, wid = tid >> 5;
    const int wm = wid & 3, wn = wid >> 2;
    const int gr = lane >> 2, tg = lane & 3;

    float acc[2][8][4];
    #pragma unroll
    for (int a = 0; a < 2; a++)
        #pragma unroll
        for (int b = 0; b < 8; b++)
            #pragma unroll
            for (int c = 0; c < 4; c++) acc[a][b][c] = 0.f;

    load_chunk(0); cp_commit();
    load_chunk(1); cp_commit();

    const int NCH = 1280 / BK;   // 40
    for (int c = 0; c < NCH; c++) {
        cp_wait1();
        __syncthreads();
        if (c + 2 < NCH) load_chunk(c + 2);
        cp_commit();

        const float* As_ = (const float*)(smem + AR_BYTES + (c % NSTAGE) * STAGE_BYTES);
        const float* Bs_ = (const float*)((const char*)As_ + B_OFF);

        #pragma unroll
        for (int ks = 0; ks < BK; ks += 8) {
            float a[2][4];
            #pragma unroll
            for (int mf = 0; mf < 2; mf++) {
                int rb = wm * 32 + mf * 16;
                a[mf][0] = As_[(rb + gr)     * ASTRIDE + ks + tg];
                a[mf][1] = As_[(rb + gr + 8) * ASTRIDE + ks + tg];
                a[mf][2] = As_[(rb + gr)     * ASTRIDE + ks + tg + 4];
                a[mf][3] = As_[(rb + gr + 8) * ASTRIDE + ks + tg + 4];
            }
            #pragma unroll
            for (int nf = 0; nf < 8; nf++) {
                int col = wn * 64 + nf * 8 + gr;
                float b0 = Bs_[(ks + tg)     * BSTRIDE + col];
                float b1 = Bs_[(ks + tg + 4) * BSTRIDE + col];
                mma_tf32(acc[0][nf], a[0], b0, b1);
                mma_tf32(acc[1][nf], a[1], b0, b1);
            }
        }
    }

    float* obase;
    if (MODE == 0) obase = se ? g_h_shared : g_h_routed;
    else           obase = se ? g_o_shared : g_o_routed;

    #pragma unroll
    for (int mf = 0; mf < 2; mf++) {
        int rb = wm * 32 + mf * 16 + gr;
        #pragma unroll
        for (int half = 0; half < 2; half++) {
            int r = rb + half * 8;
            if (m0 + r >= cnt) continue;
            float* op = obase + (size_t)(off_e + m0 + r) * 1280 + n0;
            #pragma unroll
            for (int nf = 0; nf < 8; nf++) {
                int c0 = wn * 64 + nf * 8 + 2 * tg;
                float2 v;
                v.x = acc[mf][nf][half * 2 + 0] + bias[n0 + c0];
                v.y = acc[mf][nf][half * 2 + 1] + bias[n0 + c0 + 1];
                if (MODE == 0) { v.x = gelu_exact(v.x); v.y = gelu_exact(v.y); }
                *(float2*)(op + c0) = v;
            }
        }
    }
}

// ---------------- final gather-reduce ----------------
__global__ void reduce_kernel(const float* __restrict__ x, float* __restrict__ out) {
    int t = blockIdx.x;
    size_t col = 4 * (size_t)threadIdx.x;
    float4 acc = *(const float4*)(x + (size_t)t * HDIM + col);
    float4 sh  = *(const float4*)(g_o_shared + (size_t)t * HDIM + col);
    acc.x += sh.x; acc.y += sh.y; acc.z += sh.z; acc.w += sh.w;
    #pragma unroll
    for (int k = 0; k < TOPK; k++) {
        int e   = g_eidx[t * TOPK + k];
        int p   = g_epos[t * TOPK + k];
        float g = g_gate[t * TOPK + k];
        const float4 v = *(const float4*)(g_o_routed + (size_t)(g_off[e] + p) * HDIM + col);
        acc.x += g * v.x; acc.y += g * v.y; acc.z += g * v.z; acc.w += g * v.w;
    }
    *(float4*)(out + (size_t)t * HDIM + col) = acc;
}

// ---------------------------------------------------------------------------
extern "C" void kernel_launch(void* const* d_in, const int* in_sizes, int n_in,
                              void* d_out, int out_size) {
    const float* x   = (const float*)d_in[0];
    const float* w1s = (const float*)d_in[1];
    const float* b1s = (const float*)d_in[2];
    const float* w2s = (const float*)d_in[3];
    const float* b2s = (const float*)d_in[4];
    const float* rw  = (const float*)d_in[5];
    const float* rb  = (const float*)d_in[6];
    const float* w1  = (const float*)d_in[7];
    const float* b1  = (const float*)d_in[8];
    const float* w2  = (const float*)d_in[9];
    const float* b2  = (const float*)d_in[10];
    float* out = (float*)d_out;

    cudaFuncSetAttribute(gemm_kernel<0>, cudaFuncAttributeMaxDynamicSharedMemorySize, SMEM_TOTAL);
    cudaFuncSetAttribute(gemm_kernel<1>, cudaFuncAttributeMaxDynamicSharedMemorySize, SMEM_TOTAL);

    zero_kernel<<<1, 64>>>();
    router_kernel<<<T_TOKENS / RTB, 256>>>(x, rw, rb);
    offsets_kernel<<<1, 32>>>();

    dim3 g(IDIM / BN, T_TOKENS / BM, EXPERTS + 1);   // (10, 32, 64)
    gemm_kernel<0><<<g, 256, SMEM_TOTAL>>>(x, w1, b1, w1s, b1s, w2, b2, w2s, b2s);
    gemm_kernel<1><<<g, 256, SMEM_TOTAL>>>(x, w1, b1, w1s, b1s, w2, b2, w2s, b2s);

    reduce_kernel<<<T_TOKENS, 320>>>(x, out);
}